// round 17
// baseline (speedup 1.0000x reference)
#include <cuda_runtime.h>
#include <cuda_bf16.h>

// ---------------- device scratch (no allocations allowed) ----------------
__device__ float4 g_chq[2048];      // (c,h,c,h) exact pairs (near-zone path)
__device__ float4 g_grp[520];       // (S0, 2*S1, S2, 0) per group of 8 points
__device__ float2 g_tab[6160];      // (intercept, slope) vs d2, per segment

#define HID 50

// table geometry: seg = (bits(d2) >> 16) - (81 << 7); covers exp 81..128
#define TAB_N     6144
#define TAB_OFF   10368             // 81 * 128
#define TAB_BLKS  24                // TAB_N / 256
#define MIN_D2    1.4210855e-14f    // 2^-46, folded into near-zone B2
#define D2N       0.04f             // near/far split

// linspace(0.0001, 0.9999, 1024)
#define C0f       1.0e-4f
#define STEPf     (0.9998f / 1023.0f)
#define INV_STEPf (1023.0f / 0.9998f)

// ---- scalar MUFU approx intrinsics (prep only) ----
__device__ __forceinline__ float f_rcp(float x) { float y; asm("rcp.approx.f32 %0,%1;" : "=f"(y) : "f"(x)); return y; }
__device__ __forceinline__ float f_ex2(float x) { float y; asm("ex2.approx.f32 %0,%1;" : "=f"(y) : "f"(x)); return y; }

// ---- packed f32x2 ops (sm_100+) ----
typedef unsigned long long u64;
struct f2v { u64 v; };
__device__ __forceinline__ f2v f2pack(float lo, float hi){ f2v r; asm("mov.b64 %0,{%1,%2};" : "=l"(r.v) : "f"(lo), "f"(hi)); return r; }
__device__ __forceinline__ void f2unpack(f2v a, float& lo, float& hi){ asm("mov.b64 {%0,%1},%2;" : "=f"(lo), "=f"(hi) : "l"(a.v)); }
__device__ __forceinline__ f2v f2fma(f2v a, f2v b, f2v c){ f2v r; asm("fma.rn.f32x2 %0,%1,%2,%3;" : "=l"(r.v) : "l"(a.v), "l"(b.v), "l"(c.v)); return r; }

__device__ __forceinline__ float fast_tanh(float x)
{
    float ax = fabsf(x);
    float e  = f_ex2(ax * 2.88539008f);
    float r  = f_rcp(e + 1.0f);
    float t  = fmaf(-2.0f, r, 1.0f);
    return copysignf(t, x);
}

// ---------------------------------------------------------------------------
// Accurate fp32 NR Bessel (table build only)
// ---------------------------------------------------------------------------
__device__ float bessel_j1f(float x)
{
    float ax = fabsf(x);
    if (ax < 8.0f) {
        float y = x * x;
        float num = x * (72362614232.0f + y*(-7895059235.0f + y*(242396853.1f + y*(-2972611.439f + y*(15704.48260f + y*(-30.16036606f))))));
        float den = 144725228442.0f + y*(2300535178.0f + y*(18583304.74f + y*(99447.43394f + y*(376.9991397f + y))));
        return num / den;
    }
    float z = 8.0f / ax;
    float y2 = z * z;
    float xx = ax - 2.356194491f;
    float p1 = 1.0f + y2*(0.183105e-2f + y2*(-0.3516396496e-4f + y2*(0.2457520174e-5f + y2*(-0.240337019e-6f))));
    float p2 = 0.04687499995f + y2*(-0.2002690873e-3f + y2*(0.8449199096e-5f + y2*(-0.88228987e-6f + y2*0.105787412e-6f)));
    float v = sqrtf(0.636619772f / ax) * (cosf(xx)*p1 - z*sinf(xx)*p2);
    return x < 0.0f ? -v : v;
}

__device__ float bessel_y1f(float x)
{
    float xs = fmaxf(x, 1e-12f);
    if (xs < 8.0f) {
        float y = xs * xs;
        float num = xs * (-4.900604943e13f + y*(1.275274390e13f + y*(-5.153438139e11f + y*(7.349264551e9f + y*(-4.237922726e7f + y*8.511937935e4f)))));
        float den = 2.499580570e14f + y*(4.244419664e12f + y*(3.733650367e10f + y*(2.245904002e8f + y*(1.020426050e6f + y*(3.549632885e3f + y)))));
        return num / den + 0.636619772f * (bessel_j1f(xs) * logf(xs) - 1.0f / xs);
    }
    float z = 8.0f / xs;
    float y2 = z * z;
    float xx = xs - 2.356194491f;
    float p1 = 1.0f + y2*(0.183105e-2f + y2*(-0.3516396496e-4f + y2*(0.2457520174e-5f + y2*(-0.240337019e-6f))));
    float p2 = 0.04687499995f + y2*(-0.2002690873e-3f + y2*(0.8449199096e-5f + y2*(-0.88228987e-6f + y2*0.105787412e-6f)));
    return sqrtf(0.636619772f / xs) * (sinf(xx)*p1 + z*cosf(xx)*p2);
}

__device__ __forceinline__ float green_F(int seg, float& d2_out)
{
    unsigned bits = (unsigned)(seg + TAB_OFF) << 16;
    float d2 = __uint_as_float(bits);
    d2_out = d2;
    float r  = sqrtf(d2);
    float y1 = bessel_y1f(15.0f * r);
    return y1 / (r + 1e-8f);
}

// ---------------------------------------------------------------------------
__device__ __forceinline__ void mlp_layer(const float* __restrict__ hin, float* __restrict__ hout,
                                          const float* __restrict__ W, const float* __restrict__ b, int j)
{
    if (j < HID) {
        float s = b[j];
        #pragma unroll
        for (int i = 0; i < HID; i++) s = fmaf(hin[i], W[i*HID + j], s);
        hout[j] = fast_tanh(s);
    }
}

// ---------------------------------------------------------------------------
// Kernel 1 (merged): blocks [0,TAB_BLKS) build table; rest run MLP (8 pts/block)
// and emit one group-of-8 moment vector (S0, 2S1, S2).
// ---------------------------------------------------------------------------
__global__ void __launch_bounds__(256) setup_kernel(const float* __restrict__ bp,
                            const float* __restrict__ W1, const float* __restrict__ b1,
                            const float* __restrict__ W2, const float* __restrict__ b2,
                            const float* __restrict__ W3, const float* __restrict__ b3,
                            const float* __restrict__ W4, const float* __restrict__ b4,
                            const float* __restrict__ W5, const float* __restrict__ b5,
                            int M)
{
    if (blockIdx.x < TAB_BLKS) {
        int i = blockIdx.x * 256 + threadIdx.x;
        if (i >= TAB_N) return;
        float d20, d21;
        float f0 = green_F(i, d20);
        float f1 = green_F(i + 1, d21);
        double slope = ((double)f1 - (double)f0) / ((double)d21 - (double)d20);
        double icpt  = (double)f0 - (double)d20 * slope;
        g_tab[i] = make_float2((float)icpt, (float)slope);
        return;
    }

    __shared__ float hs[8][2][HID + 2];
    __shared__ float sc[8], sh[8];
    int warp = threadIdx.x >> 5;
    int lane = threadIdx.x & 31;
    int blk  = blockIdx.x - TAB_BLKS;
    int m = blk * 8 + warp;
    bool active = m < M;

    float* ha = hs[warp][0];
    float* hb = hs[warp][1];

    if (active) {
        float x0 = bp[2*m + 0];
        float x1 = bp[2*m + 1];
        int j0 = lane, j1 = lane + 32;

        {
            float s = fmaf(x0, W1[j0], fmaf(x1, W1[HID + j0], b1[j0]));
            ha[j0] = fast_tanh(s);
            if (j1 < HID) {
                float s2 = fmaf(x0, W1[j1], fmaf(x1, W1[HID + j1], b1[j1]));
                ha[j1] = fast_tanh(s2);
            }
        }
        __syncwarp();
        mlp_layer(ha, hb, W2, b2, j0); mlp_layer(ha, hb, W2, b2, j1); __syncwarp();
        mlp_layer(hb, ha, W3, b3, j0); mlp_layer(hb, ha, W3, b3, j1); __syncwarp();
        mlp_layer(ha, hb, W4, b4, j0); mlp_layer(ha, hb, W4, b4, j1); __syncwarp();

        float s = hb[j0] * W5[j0];
        if (j1 < HID) s = fmaf(hb[j1], W5[j1], s);
        #pragma unroll
        for (int o = 16; o > 0; o >>= 1) s += __shfl_xor_sync(0xFFFFFFFFu, s, o);

        if (lane == 0) {
            float c = (m < 2048) ? x0 : x1;   // sides 0,1 use x; sides 2,3 use y
            float h = s + b5[0];
            ((float2*)g_chq)[m] = make_float2(c, h);
            sc[warp] = c; sh[warp] = h;
        }
    }
    __syncthreads();

    // one group-of-8 moment vector per block
    if (threadIdx.x == 0 && blk * 8 < M) {
        float S0 = 0.0f, S1 = 0.0f, S2 = 0.0f;
        #pragma unroll
        for (int t = 0; t < 8; t++) {
            float c = sc[t], h = sh[t];
            S0 += h;
            S1 = fmaf(c, h, S1);
            S2 = fmaf(c*c, h, S2);
        }
        g_grp[blk] = make_float4(S0, 2.0f*S1, S2, 0.0f);
    }
}

// ---------------------------------------------------------------------------
// Far segment via group-of-8 moments: 1 lookup per 8 pairs, evaluated at the
// group midpoint; Σ F(d2_i) h_i = a*S0 + b*(A^2 S0 - 2A S1 + S2 + B2 S0).
// Group range [begG, endG) in units of 8 points; lane strides 32.
// ---------------------------------------------------------------------------
__device__ __forceinline__ float far_grp(const float2* __restrict__ tabm,
                                         float A, float B2, int begG, int endG,
                                         int baseG, int lane)
{
    float a0 = 0.0f, a1 = 0.0f;
    int g0 = begG + lane;
    if (g0 < endG) {
        // group midpoint coordinate: C0 + (8g + 3.5)*step
        float dxm = A - fmaf((float)g0, 8.0f*STEPf, C0f + 3.5f*STEPf);
        const float dstep = -256.0f*STEPf;
        #pragma unroll 4
        for (int g = g0; g < endG; g += 32) {
            float4 s = g_grp[baseG + g];
            float d2m = fmaf(dxm, dxm, B2);
            dxm += dstep;
            float2 e = tabm[__float_as_uint(d2m) >> 16];
            float q = fmaf(A, s.x, -s.y);        // A*S0 - 2*S1
            float w = fmaf(A, q, s.z);           // A^2 S0 - 2A S1 + S2
            w = fmaf(B2, s.x, w);                // + B2*S0
            a0 = fmaf(e.x, s.x, a0);
            a1 = fmaf(e.y, w, a1);
        }
    }
    return a0 + a1;
}

// ---------------------------------------------------------------------------
// Near-exact segment: one lookup per pair; exact c from input.
// ---------------------------------------------------------------------------
__device__ __forceinline__ float near_seg(const float2* __restrict__ tabm,
                                          float A, float B2m, int beg, int end,
                                          int base, int lane)
{
    float a0 = 0.0f, a1 = 0.0f;
    f2v Ap  = f2pack(A, A);
    f2v B2p = f2pack(B2m, B2m);
    f2v neg1 = f2pack(-1.0f, -1.0f);
    for (int i = beg + 2*lane; i < end; i += 64) {
        float4 v = g_chq[(base + i) >> 1];
        f2v c  = f2pack(v.x, v.z);
        f2v dx = f2fma(c, neg1, Ap);
        f2v d2p = f2fma(dx, dx, B2p);
        float d20, d21; f2unpack(d2p, d20, d21);
        float2 e0 = tabm[__float_as_uint(d20) >> 16];
        float2 e1 = tabm[__float_as_uint(d21) >> 16];
        float F0 = fmaf(d20, e0.y, e0.x);
        float F1 = fmaf(d21, e1.y, e1.x);
        a0 = fmaf(F0, v.y, a0);
        a1 = fmaf(F1, v.w, a1);
    }
    return a0 + a1;
}

// ---------------------------------------------------------------------------
// Full side: far groups [0,ilo/8) + near [ilo,ihi) + far groups [ihi/8,128).
// ---------------------------------------------------------------------------
__device__ __forceinline__ float side_sum(const float2* __restrict__ tabm,
                                          float A, float B, int side, int lane)
{
    float B2 = B * B;
    int ilo = 0, ihi = 0;
    float w2 = D2N - B2;
    if (w2 > 0.0f) {
        float w = sqrtf(w2);
        ilo = (int)floorf((A - w - C0f) * INV_STEPf) - 1;
        ihi = (int)ceilf((A + w - C0f) * INV_STEPf) + 2;
        ilo = max(ilo, 0);
        ihi = min(ihi, 1024);
        ilo &= ~7;                       // 8-align
        ihi = (ihi + 7) & ~7;            // 8-align
        ihi = min(ihi, 1024);
        if (ihi < ilo) ihi = ilo;
    }
    float s = 0.0f;
    s += far_grp(tabm, A, B2, 0, ilo >> 3, side * 128, lane);
    s += near_seg(tabm, A, B2 + MIN_D2, ilo, ihi, side * 1024, lane);
    s += far_grp(tabm, A, B2, ihi >> 3, 128, side * 128, lane);
    return s;
}

// ---------------------------------------------------------------------------
// Kernel 2: warp-per-point, 16 warps/block, smem-resident table.
// ---------------------------------------------------------------------------
__global__ void __launch_bounds__(512, 3) pair_kernel(const float* __restrict__ points,
                                                      const float* __restrict__ dyp,
                                                      float* __restrict__ out,
                                                      int P)
{
    __shared__ float2 tab[TAB_N];    // 48 KB
    int tid = threadIdx.x;

    {
        const float4* src = (const float4*)g_tab;
        float4* dst = (float4*)tab;
        #pragma unroll
        for (int j = tid; j < TAB_N / 2; j += 512) dst[j] = src[j];
    }
    __syncthreads();

    int pt   = blockIdx.x * 16 + (tid >> 5);
    int lane = tid & 31;
    if (pt >= P) return;

    const float2* tabm = tab - TAB_OFF;

    float px = points[2*pt + 0];
    float py = points[2*pt + 1];

    float Bt = py - 1.0f;   // top:    dot = py-1
    float Bb = py;          // bottom: dot = -py
    float Bl = px;          // left:   dot = -px
    float Br = px - 1.0f;   // right:  dot = px-1

    float s0 = side_sum(tabm, px, Bt, 0, lane);
    float s1 = side_sum(tabm, px, Bb, 1, lane);
    float s2 = side_sum(tabm, py, Bl, 2, lane);
    float s3 = side_sum(tabm, py, Br, 3, lane);

    float total = Bt*s0 - Bb*s1 - Bl*s2 + Br*s3;

    #pragma unroll
    for (int o = 16; o > 0; o >>= 1)
        total += __shfl_xor_sync(0xFFFFFFFFu, total, o);

    if (lane == 0) out[pt] = total * (3.75f * dyp[0]);   // 0.25 * k * dy
}

// ---------------------------------------------------------------------------
extern "C" void kernel_launch(void* const* d_in, const int* in_sizes, int n_in,
                              void* d_out, int out_size)
{
    const float* points = (const float*)d_in[0];
    const float* bp     = (const float*)d_in[1];
    const float* dyp    = (const float*)d_in[3];
    const float* W1 = (const float*)d_in[4];
    const float* b1 = (const float*)d_in[5];
    const float* W2 = (const float*)d_in[6];
    const float* b2 = (const float*)d_in[7];
    const float* W3 = (const float*)d_in[8];
    const float* b3 = (const float*)d_in[9];
    const float* W4 = (const float*)d_in[10];
    const float* b4 = (const float*)d_in[11];
    const float* W5 = (const float*)d_in[12];
    const float* b5 = (const float*)d_in[13];

    int P = in_sizes[0] / 2;
    int M = in_sizes[1] / 2;

    int prep_blocks = (M + 7) / 8;
    setup_kernel<<<TAB_BLKS + prep_blocks, 256>>>(bp, W1, b1, W2, b2, W3, b3, W4, b4, W5, b5, M);

    int blocks = (P + 15) / 16;
    pair_kernel<<<blocks, 512>>>(points, dyp, (float*)d_out, P);
}